// round 17
// baseline (speedup 1.0000x reference)
#include <cuda_runtime.h>
#include <cuda_bf16.h>
#include <stdint.h>

// Problem constants
#define PB   8
#define PN   1024
#define PD   768
#define PH   12
#define PHD  64
#define PM   (PB * PN)        // 8192
#define PQKV (3 * PD)         // 2304
#define PKP  (PD / 2)         // 384 k-pairs
#define PSCALE 0.125f         // 64^-0.5

// ---------------------------------------------------------------------------
// Scratch (allocation-free rule: __device__ globals). All "packed" arrays hold
// bf16x2 words: low 16 bits = even-k element, high = odd-k (MMA frag format).
// ---------------------------------------------------------------------------
__device__ unsigned g_xp_h[(size_t)PM * PKP];      // x packed   [M][K/2]
__device__ unsigned g_xp_l[(size_t)PM * PKP];
__device__ unsigned g_wqkv_h[(size_t)PKP * PQKV];  // w_qkv      [K/2][NC]
__device__ unsigned g_wqkv_l[(size_t)PKP * PQKV];
__device__ unsigned g_wproj_h[(size_t)PKP * PD];   // w_proj     [K/2][NC]
__device__ unsigned g_wproj_l[(size_t)PKP * PD];
#define BHN32 ((size_t)PB * PH * PN * 32)
__device__ unsigned g_qp_h[BHN32], g_qp_l[BHN32];  // Q [B,H,N][32 d-pairs]
__device__ unsigned g_kp_h[BHN32], g_kp_l[BHN32];  // K same
__device__ unsigned g_vp_h[BHN32], g_vp_l[BHN32];  // V same (pairs along d)
__device__ unsigned g_cx_h[(size_t)PM * PKP];      // ctx packed [M][D/2]
__device__ unsigned g_cx_l[(size_t)PM * PKP];

// ---------------------------------------------------------------------------
// Helpers
// ---------------------------------------------------------------------------
// Split (x0,x1) -> packed bf16x2 hi word + bf16x2 lo (residual) word. x0 low.
__device__ __forceinline__ void split2(float x0, float x1, unsigned& h, unsigned& l)
{
    unsigned hh;
    asm("cvt.rn.bf16x2.f32 %0, %1, %2;" : "=r"(hh) : "f"(x1), "f"(x0));
    float h0 = __uint_as_float(hh << 16);
    float h1 = __uint_as_float(hh & 0xffff0000u);
    unsigned ll;
    asm("cvt.rn.bf16x2.f32 %0, %1, %2;" : "=r"(ll) : "f"(x1 - h1), "f"(x0 - h0));
    h = hh; l = ll;
}

__device__ __forceinline__ unsigned prmt(unsigned a, unsigned b, unsigned sel)
{
    unsigned r;
    asm("prmt.b32 %0, %1, %2, %3;" : "=r"(r) : "r"(a), "r"(b), "r"(sel));
    return r;
}

// bf16 warp MMA: D += A(16x16) * B(16x8), fp32 accumulate. m16n8k16.
// A frag (row-major, k-pairs packed): a0=(g,2t:2t+1) a1=(g+8,..) a2=(g,2t+8:2t+9)
// a3=(g+8,..)   B frag (col-major): b0=(k=2t:2t+1,n=g) b1=(k=2t+8:2t+9,n=g)
// C/D: c0=(g,2t) c1=(g,2t+1) c2=(g+8,2t) c3=(g+8,2t+1)   [g=lane>>2, t=lane&3]
__device__ __forceinline__ void mma16(float* d, const unsigned* a, const unsigned* b)
{
    asm volatile(
        "mma.sync.aligned.m16n8k16.row.col.f32.bf16.bf16.f32 "
        "{%0,%1,%2,%3}, {%4,%5,%6,%7}, {%8,%9}, {%0,%1,%2,%3};\n"
        : "+f"(d[0]), "+f"(d[1]), "+f"(d[2]), "+f"(d[3])
        : "r"(a[0]), "r"(a[1]), "r"(a[2]), "r"(a[3]), "r"(b[0]), "r"(b[1]));
}

// ---------------------------------------------------------------------------
// Pre-pass 1: pack x[M][D] -> hi/lo pair-words [M][D/2]
// ---------------------------------------------------------------------------
__global__ __launch_bounds__(PKP) void pack_x(const float* __restrict__ x)
{
    const int m  = blockIdx.x;
    const int kp = threadIdx.x;
    float2 v = *(const float2*)(x + (size_t)m * PD + 2 * kp);
    unsigned h, l;
    split2(v.x, v.y, h, l);
    g_xp_h[(size_t)m * PKP + kp] = h;
    g_xp_l[(size_t)m * PKP + kp] = l;
}

// Pre-pass 2: pack W[K][NC] -> hi/lo pair-words [K/2][NC] (pairs along K)
__global__ __launch_bounds__(256) void pack_w(
    const float* __restrict__ W, unsigned* __restrict__ Th,
    unsigned* __restrict__ Tl, int NC)
{
    const int n  = blockIdx.x * 256 + threadIdx.x;
    const int kp = blockIdx.y;
    float w0 = W[(size_t)(2 * kp) * NC + n];
    float w1 = W[(size_t)(2 * kp + 1) * NC + n];
    unsigned h, l;
    split2(w0, w1, h, l);
    Th[(size_t)kp * NC + n] = h;
    Tl[(size_t)kp * NC + n] = l;
}

// ---------------------------------------------------------------------------
// bf16x3 GEMM (mma.sync), double-buffered, COPY-ONLY tile fills.
// C = A @ W + bias. Tile 128x128x32 (16 kp), 8 warps (2x4), warp 64x32.
// MODE 0: A=g_xp, B=g_wqkv, epilogue packs+scatters Q/K/V (bf16 hi/lo pairs).
// MODE 1: A=g_cx, B=g_wproj, epilogue writes fp32 C (d_out).
// SMEM word layout: Ah/Al[row][kp] stride 20 (banks 20g+tq distinct);
// Bh/Bl[kp][n] stride 136 == 8 mod 32 (banks 8tq+g distinct).
// ---------------------------------------------------------------------------
#define SAW 20
#define SBW 136
#define AWRD (128 * SAW)
#define BWRD (16 * SBW)
#define BUFW (2 * AWRD + 2 * BWRD)
#define GSMEM (2 * BUFW * 4)

template <int MODE>
__global__ __launch_bounds__(256) void gemm_tc(
    const float* __restrict__ bias, float* __restrict__ C, int NC)
{
    extern __shared__ unsigned dsm[];

    const unsigned* Aph = (MODE == 0) ? g_xp_h : g_cx_h;
    const unsigned* Apl = (MODE == 0) ? g_xp_l : g_cx_l;
    const unsigned* Bph = (MODE == 0) ? g_wqkv_h : g_wproj_h;
    const unsigned* Bpl = (MODE == 0) ? g_wqkv_l : g_wproj_l;

    const int m0 = blockIdx.y * 128;
    const int n0 = blockIdx.x * 128;
    const int t    = threadIdx.x;
    const int lane = t & 31;
    const int w    = t >> 5;
    const int wm   = w >> 2;
    const int wn   = w & 3;
    const int g    = lane >> 2;
    const int tq   = lane & 3;

    float acc[4][4][4];
#pragma unroll
    for (int i = 0; i < 4; i++)
#pragma unroll
        for (int j = 0; j < 4; j++)
#pragma unroll
            for (int c = 0; c < 4; c++) acc[i][j][c] = 0.f;

    const int arow = t >> 1;         // 0..127
    const int aoff = (t & 1) * 8;    // word offset in 16-word row
    const int brow = t >> 4;         // 0..15
    const int boff = (t & 15) * 8;   // word offset in 128-word row

    const int NT = PKP / 16;         // 24 k-tiles of 32 k

    uint4 aRh[2], aRl[2], bRh[2], bRl[2];

    auto ldg_tile = [&](int kt) {
        size_t ab = (size_t)(m0 + arow) * PKP + kt * 16 + aoff;
        aRh[0] = *(const uint4*)(Aph + ab);
        aRh[1] = *(const uint4*)(Aph + ab + 4);
        aRl[0] = *(const uint4*)(Apl + ab);
        aRl[1] = *(const uint4*)(Apl + ab + 4);
        size_t bb = (size_t)(kt * 16 + brow) * NC + n0 + boff;
        bRh[0] = *(const uint4*)(Bph + bb);
        bRh[1] = *(const uint4*)(Bph + bb + 4);
        bRl[0] = *(const uint4*)(Bpl + bb);
        bRl[1] = *(const uint4*)(Bpl + bb + 4);
    };

    auto store_tile = [&](int bi) {
        unsigned* AhP = dsm + bi * BUFW;
        unsigned* AlP = AhP + AWRD;
        unsigned* BhP = AlP + AWRD;
        unsigned* BlP = BhP + BWRD;
        *(uint4*)&AhP[arow * SAW + aoff]     = aRh[0];
        *(uint4*)&AhP[arow * SAW + aoff + 4] = aRh[1];
        *(uint4*)&AlP[arow * SAW + aoff]     = aRl[0];
        *(uint4*)&AlP[arow * SAW + aoff + 4] = aRl[1];
        *(uint4*)&BhP[brow * SBW + boff]     = bRh[0];
        *(uint4*)&BhP[brow * SBW + boff + 4] = bRh[1];
        *(uint4*)&BlP[brow * SBW + boff]     = bRl[0];
        *(uint4*)&BlP[brow * SBW + boff + 4] = bRl[1];
    };

    ldg_tile(0);
    store_tile(0);
    __syncthreads();

    for (int kt = 0; kt < NT; kt++) {
        if (kt + 1 < NT) ldg_tile(kt + 1);   // hidden under MMAs

        const unsigned* AhP = dsm + (kt & 1) * BUFW;
        const unsigned* AlP = AhP + AWRD;
        const unsigned* BhP = AlP + AWRD;
        const unsigned* BlP = BhP + BWRD;

#pragma unroll
        for (int ks = 0; ks < 2; ks++) {
            unsigned ah[4][4], al[4][4];
#pragma unroll
            for (int mt = 0; mt < 4; mt++) {
                int r  = wm * 64 + mt * 16 + g;
                int kq = ks * 8 + tq;
                ah[mt][0] = AhP[r * SAW + kq];           al[mt][0] = AlP[r * SAW + kq];
                ah[mt][1] = AhP[(r + 8) * SAW + kq];     al[mt][1] = AlP[(r + 8) * SAW + kq];
                ah[mt][2] = AhP[r * SAW + kq + 4];       al[mt][2] = AlP[r * SAW + kq + 4];
                ah[mt][3] = AhP[(r + 8) * SAW + kq + 4]; al[mt][3] = AlP[(r + 8) * SAW + kq + 4];
            }
#pragma unroll
            for (int nt = 0; nt < 4; nt++) {
                int cc = wn * 32 + nt * 8 + g;
                unsigned bh[2], bl[2];
                bh[0] = BhP[(ks * 8 + tq) * SBW + cc];     bl[0] = BlP[(ks * 8 + tq) * SBW + cc];
                bh[1] = BhP[(ks * 8 + tq + 4) * SBW + cc]; bl[1] = BlP[(ks * 8 + tq + 4) * SBW + cc];
#pragma unroll
                for (int mt = 0; mt < 4; mt++) {
                    mma16(acc[mt][nt], ah[mt], bh);   // hi*hi
                    mma16(acc[mt][nt], al[mt], bh);   // lo*hi
                    mma16(acc[mt][nt], ah[mt], bl);   // hi*lo
                }
            }
        }

        if (kt + 1 < NT) store_tile((kt + 1) & 1);
        __syncthreads();
    }

    // Epilogue
#pragma unroll
    for (int mt = 0; mt < 4; mt++) {
#pragma unroll
        for (int nt = 0; nt < 4; nt++) {
            int rm = m0 + wm * 64 + mt * 16 + g;
            int cn = n0 + wn * 32 + nt * 8 + 2 * tq;
            float v0 = acc[mt][nt][0] + bias[cn];
            float v1 = acc[mt][nt][1] + bias[cn + 1];
            float v2 = acc[mt][nt][2] + bias[cn];       // row rm+8
            float v3 = acc[mt][nt][3] + bias[cn + 1];
            if (MODE == 0) {
                // Pack pairs (cn even, cn+1 same head) -> bf16 hi/lo words
                unsigned h01, l01, h23, l23;
                split2(v0, v1, h01, l01);
                split2(v2, v3, h23, l23);
                int which = cn / PD;                    // 0=q 1=k 2=v
                int d  = cn - which * PD;
                int hh = d >> 6;
                int dp = (d & 63) >> 1;
                int bb = rm >> 10;
                int nn = rm & 1023;
                unsigned* dh = (which == 0) ? g_qp_h : ((which == 1) ? g_kp_h : g_vp_h);
                unsigned* dl = (which == 0) ? g_qp_l : ((which == 1) ? g_kp_l : g_vp_l);
                size_t base = ((size_t)(bb * PH + hh) * PN + nn) * 32 + dp;
                dh[base] = h01;          dl[base] = l01;
                dh[base + 8 * 32] = h23; dl[base + 8 * 32] = l23;   // row rm+8
            } else {
                float2 lo; lo.x = v0; lo.y = v1;
                float2 hi; hi.x = v2; hi.y = v3;
                *(float2*)&C[(size_t)rm * NC + cn]       = lo;
                *(float2*)&C[(size_t)(rm + 8) * NC + cn] = hi;
            }
        }
    }
}

// ---------------------------------------------------------------------------
// Flash attention, bf16x3 m16n8k16, copy-only K fill, PRMT V repack.
// Block = (64 q-rows, head, batch), 4 warps; warp w owns rows [16w,16w+16).
// Kh/Kl[key][dp]: pairs along d.  Vh/Vl[d][kp]: pairs along key (PRMT-built).
// PSCALE folded into S post-MMA. Output written packed for gemm1.
// ---------------------------------------------------------------------------
#define SKW 36

__global__ __launch_bounds__(128) void attn_tc()
{
    __shared__ unsigned Kh[64][SKW], Kl[64][SKW];
    __shared__ unsigned Vh[64][SKW], Vl[64][SKW];

    const int t    = threadIdx.x;
    const int lane = t & 31;
    const int w    = t >> 5;
    const int g    = lane >> 2;
    const int tq   = lane & 3;

    const int qt = blockIdx.x;
    const int h  = blockIdx.y;
    const int b  = blockIdx.z;
    const size_t head32 = ((size_t)(b * PH + h)) * PN * 32;

    // Q fragments: direct word loads from packed global (no scale, no split)
    unsigned qh[4][4], ql[4][4];
    {
        const unsigned* Qh = g_qp_h + head32 + (size_t)(qt * 64 + w * 16) * 32;
        const unsigned* Ql = g_qp_l + head32 + (size_t)(qt * 64 + w * 16) * 32;
#pragma unroll
        for (int ks = 0; ks < 4; ks++) {
            int dp = ks * 8 + tq;
            qh[ks][0] = Qh[g * 32 + dp];           ql[ks][0] = Ql[g * 32 + dp];
            qh[ks][1] = Qh[(g + 8) * 32 + dp];     ql[ks][1] = Ql[(g + 8) * 32 + dp];
            qh[ks][2] = Qh[g * 32 + dp + 4];       ql[ks][2] = Ql[g * 32 + dp + 4];
            qh[ks][3] = Qh[(g + 8) * 32 + dp + 4]; ql[ks][3] = Ql[(g + 8) * 32 + dp + 4];
        }
    }

    float o[8][4];
#pragma unroll
    for (int nt = 0; nt < 8; nt++)
#pragma unroll
        for (int c = 0; c < 4; c++) o[nt][c] = 0.f;
    float m0v = -1e30f, m1v = -1e30f;
    float l0 = 0.f, l1 = 0.f;

    // K fill: thread t handles row t>>1, 16-word half (t&1)
    const int krow = t >> 1;
    const int kseg = (t & 1) * 16;
    // V fill lane decomposition
    const int vkq = lane & 3;
    const int vdq = lane >> 2;
    const int vd0 = 2 * vdq + 16 * w;
    const int vdp = vdq + 8 * w;

    uint4 kRh[4], kRl[4];
    unsigned vW[8][4];                 // {w0h, w1h, w0l, w1l} per i

    auto ldg_kv = [&](int kt) {
        const uint4* Kgh = (const uint4*)(g_kp_h + head32 + (size_t)kt * 64 * 32);
        const uint4* Kgl = (const uint4*)(g_kp_l + head32 + (size_t)kt * 64 * 32);
        int u0 = krow * 8 + (t & 1) * 4;
#pragma unroll
        for (int j = 0; j < 4; j++) { kRh[j] = Kgh[u0 + j]; kRl[j] = Kgl[u0 + j]; }
        const unsigned* Vgh = g_vp_h + head32 + (size_t)kt * 64 * 32;
        const unsigned* Vgl = g_vp_l + head32 + (size_t)kt * 64 * 32;
#pragma unroll
        for (int i = 0; i < 8; i++) {
            int kp = vkq + 4 * i;
            vW[i][0] = Vgh[(size_t)(2 * kp) * 32 + vdp];
            vW[i][1] = Vgh[(size_t)(2 * kp + 1) * 32 + vdp];
            vW[i][2] = Vgl[(size_t)(2 * kp) * 32 + vdp];
            vW[i][3] = Vgl[(size_t)(2 * kp + 1) * 32 + vdp];
        }
    };

    auto store_kv = [&]() {
#pragma unroll
        for (int j = 0; j < 4; j++) {
            *(uint4*)&Kh[krow][kseg + 4 * j] = kRh[j];
            *(uint4*)&Kl[krow][kseg + 4 * j] = kRl[j];
        }
#pragma unroll
        for (int i = 0; i < 8; i++) {
            int kp = vkq + 4 * i;
            // (even-key low, odd-key high) per d
            Vh[vd0][kp]     = prmt(vW[i][0], vW[i][1], 0x5410);
            Vh[vd0 + 1][kp] = prmt(vW[i][0], vW[i][1], 0x7632);
            Vl[vd0][kp]     = prmt(vW[i][2], vW[i][3], 0x5410);
            Vl[vd0 + 1][kp] = prmt(vW[i][2], vW[i][3], 0x7632);
        }
    };

    ldg_kv(0);

    for (int kt = 0; kt < PN / 64; kt++) {
        store_kv();
        __syncthreads();
        if (kt + 1 < PN / 64) ldg_kv(kt + 1);

        // S = Q @ K^T (3-MMA compensated), 16 rows x 64 keys
        float s[8][4];
#pragma unroll
        for (int nt = 0; nt < 8; nt++)
#pragma unroll
            for (int c = 0; c < 4; c++) s[nt][c] = 0.f;

#pragma unroll
        for (int nt = 0; nt < 8; nt++) {
            int key = nt * 8 + g;
#pragma unroll
            for (int ks = 0; ks < 4; ks++) {
                unsigned bh[2], bl[2];
                bh[0] = Kh[key][ks * 8 + tq];     bl[0] = Kl[key][ks * 8 + tq];
                bh[1] = Kh[key][ks * 8 + tq + 4]; bl[1] = Kl[key][ks * 8 + tq + 4];
                mma16(s[nt], qh[ks], bh);
                mma16(s[nt], ql[ks], bh);
                mma16(s[nt], qh[ks], bl);
            }
        }

        // Scale + online softmax (rows r0 = w*16+g, r1 = r0+8)
        float tmax0 = -1e30f, tmax1 = -1e30f;
#pragma unroll
        for (int nt = 0; nt < 8; nt++) {
            s[nt][0] *= PSCALE; s[nt][1] *= PSCALE;
            s[nt][2] *= PSCALE; s[nt][3] *= PSCALE;
            tmax0 = fmaxf(tmax0, fmaxf(s[nt][0], s[nt][1]));
            tmax1 = fmaxf(tmax1, fmaxf(s[nt][2], s[nt][3]));
        }
        tmax0 = fmaxf(tmax0, __shfl_xor_sync(0xffffffffu, tmax0, 1));
        tmax0 = fmaxf(tmax0, __shfl_xor_sync(0xffffffffu, tmax0, 2));
        tmax1 = fmaxf(tmax1, __shfl_xor_sync(0xffffffffu, tmax1, 1));
        tmax1 = fmaxf(tmax1, __shfl_xor_sync(0xffffffffu, tmax1, 2));

        float mnew0 = fmaxf(m0v, tmax0);
        float mnew1 = fmaxf(m1v, tmax1);
        float corr0 = __expf(m0v - mnew0);
        float corr1 = __expf(m1v - mnew1);
#pragma unroll
        for (int nt = 0; nt < 8; nt++) {
            o[nt][0] *= corr0; o[nt][1] *= corr0;
            o[nt][2] *= corr1; o[nt][3] *= corr1;
        }

        float rs0 = 0.f, rs1 = 0.f;
#pragma unroll
        for (int nt = 0; nt < 8; nt++) {
            s[nt][0] = __expf(s[nt][0] - mnew0);
            s[nt][1] = __expf(s[nt][1] - mnew0);
            s[nt][2] = __expf(s[nt][2] - mnew1);
            s[nt][3] = __expf(s[nt][3] - mnew1);
            rs0 += s[nt][0] + s[nt][1];
            rs1 += s[nt][2] + s[nt][3];
        }
        rs0 += __shfl_xor_sync(0xffffffffu, rs0, 1);
        rs0 += __shfl_xor_sync(0xffffffffu, rs0, 2);
        rs1 += __shfl_xor_sync(0xffffffffu, rs1, 1);
        rs1 += __shfl_xor_sync(0xffffffffu, rs1, 2);
        l0 = l0 * corr0 + rs0;
        l1 = l1 * corr1 + rs1;
        m0v = mnew0;
        m1v = mnew1;

        // O += P @ V. P frags straight from s registers (split to bf16 hi/lo).
#pragma unroll
        for (int ks = 0; ks < 4; ks++) {
            unsigned ah[4], al[4];
            split2(s[2 * ks][0],     s[2 * ks][1],     ah[0], al[0]);
            split2(s[2 * ks][2],     s[2 * ks][3],     ah[1], al[1]);
            split2(s[2 * ks + 1][0], s[2 * ks + 1][1], ah[2], al[2]);
            split2(s[2 * ks + 1][2], s[2 * ks + 1][3], ah[3], al[3]);
#pragma unroll
            for (int nt = 0; nt < 8; nt++) {
                int dcol = nt * 8 + g;
                unsigned bh[2], bl[2];
                bh[0] = Vh[dcol][ks * 8 + tq];     bl[0] = Vl[dcol][ks * 8 + tq];
                bh[1] = Vh[dcol][ks * 8 + tq + 4]; bl[1] = Vl[dcol][ks * 8 + tq + 4];
                mma16(o[nt], ah, bh);
                mma16(o[nt], al, bh);
                mma16(o[nt], ah, bl);
            }
        }
        __syncthreads();
    }

    // Normalize and write ctx PACKED (hi/lo bf16 pair words) for gemm1
    float inv0 = 1.f / l0;
    float inv1 = 1.f / l1;
    unsigned* Ch = g_cx_h + ((size_t)(b * PN) + qt * 64 + w * 16 + g) * PKP + h * 32;
    unsigned* Cl = g_cx_l + ((size_t)(b * PN) + qt * 64 + w * 16 + g) * PKP + h * 32;
#pragma unroll
    for (int nt = 0; nt < 8; nt++) {
        int cp = nt * 4 + tq;
        unsigned hw, lw;
        split2(o[nt][0] * inv0, o[nt][1] * inv0, hw, lw);
        Ch[cp] = hw; Cl[cp] = lw;
        split2(o[nt][2] * inv1, o[nt][3] * inv1, hw, lw);
        Ch[(size_t)8 * PKP + cp] = hw; Cl[(size_t)8 * PKP + cp] = lw;   // row g+8
    }
}

// ---------------------------------------------------------------------------
extern "C" void kernel_launch(void* const* d_in, const int* in_sizes, int n_in,
                              void* d_out, int out_size)
{
    const float* x      = (const float*)d_in[0];
    const float* w_qkv  = (const float*)d_in[1];
    const float* b_qkv  = (const float*)d_in[2];
    const float* w_proj = (const float*)d_in[3];
    const float* b_proj = (const float*)d_in[4];
    float* out = (float*)d_out;

    (void)in_sizes; (void)n_in; (void)out_size;

    static bool attr_done = false;
    if (!attr_done) {
        cudaFuncSetAttribute((const void*)gemm_tc<0>,
                             cudaFuncAttributeMaxDynamicSharedMemorySize, GSMEM);
        cudaFuncSetAttribute((const void*)gemm_tc<1>,
                             cudaFuncAttributeMaxDynamicSharedMemorySize, GSMEM);
        attr_done = true;
    }

    static unsigned *p_wqkv_h = nullptr, *p_wqkv_l, *p_wproj_h, *p_wproj_l;
    if (!p_wqkv_h) {
        cudaGetSymbolAddress((void**)&p_wqkv_h, g_wqkv_h);
        cudaGetSymbolAddress((void**)&p_wqkv_l, g_wqkv_l);
        cudaGetSymbolAddress((void**)&p_wproj_h, g_wproj_h);
        cudaGetSymbolAddress((void**)&p_wproj_l, g_wproj_l);
    }

    // 0) Pre-passes: pack x and weights into bf16 hi/lo pair-words
    pack_x<<<PM, PKP>>>(x);
    pack_w<<<dim3(PQKV / 256, PKP), 256>>>(w_qkv, p_wqkv_h, p_wqkv_l, PQKV);
    pack_w<<<dim3(PD / 256, PKP), 256>>>(w_proj, p_wproj_h, p_wproj_l, PD);

    // 1) QKV projection -> packed/scattered Q,K,V
    gemm_tc<0><<<dim3(PQKV / 128, PM / 128), 256, GSMEM>>>(b_qkv, nullptr, PQKV);

    // 2) Attention -> packed ctx
    attn_tc<<<dim3(PN / 64, PH, PB), 128>>>();

    // 3) Output projection -> d_out (fp32)
    gemm_tc<1><<<dim3(PD / 128, PM / 128), 256, GSMEM>>>(b_proj, out, PD);
}